// round 16
// baseline (speedup 1.0000x reference)
#include <cuda_runtime.h>
#include <cuda_bf16.h>

typedef unsigned long long u64;
typedef unsigned int u32;

#define Bc 256
#define Tc 1024
#define Hc 128
#define Gc 512
#define Mc (Bc*Tc)

// Scratch (device globals: sanctioned workaround for the no-alloc rule)
__device__ float g_xg[(size_t)Mc * Gc];    // [B*T, 512] gate preactivations
__device__ float g_h0s[(size_t)Mc * Hc];   // [B*T, 128] layer-0 hidden states
__device__ __nv_bfloat16 g_whi0[Gc * 64];  // w_ih_0 bf16 hi
__device__ __nv_bfloat16 g_wlo0[Gc * 64];  // w_ih_0 bf16 lo
__device__ __nv_bfloat16 g_whi1[Gc * Hc];  // w_ih_1 bf16 hi
__device__ __nv_bfloat16 g_wlo1[Gc * Hc];  // w_ih_1 bf16 lo

// ---------- packed f32x2 helpers ----------
static __device__ __forceinline__ u64 ffma2(u64 a, u64 b, u64 c) {
    u64 d; asm("fma.rn.f32x2 %0, %1, %2, %3;" : "=l"(d) : "l"(a), "l"(b), "l"(c)); return d;
}
static __device__ __forceinline__ float red2(u64 v) {
    u32 a, b; asm("mov.b64 {%0, %1}, %2;" : "=r"(a), "=r"(b) : "l"(v));
    return __uint_as_float(a) + __uint_as_float(b);
}
static __device__ __forceinline__ float sigf(float x) {
    return __fdividef(1.f, 1.f + __expf(-x));
}
static __device__ __forceinline__ float tanh_f(float x) {
    return 1.f - __fdividef(2.f, 1.f + __expf(2.f * x));
}

// ---------- mma.sync helpers (baseline PTX, sm_80+) ----------
static __device__ __forceinline__ u32 smem_u32(const void* p) {
    u32 a;
    asm("{ .reg .u64 t; cvta.to.shared.u64 t, %1; cvt.u32.u64 %0, t; }"
        : "=r"(a) : "l"(p));
    return a;
}
static __device__ __forceinline__ void ldm_x4(u32* r, u32 a) {
    asm volatile("ldmatrix.sync.aligned.m8n8.x4.shared.b16 {%0,%1,%2,%3}, [%4];"
        : "=r"(r[0]), "=r"(r[1]), "=r"(r[2]), "=r"(r[3]) : "r"(a));
}
static __device__ __forceinline__ void mma16816(float* d, const u32* a, const u32* b) {
    asm volatile(
        "mma.sync.aligned.m16n8k16.row.col.f32.bf16.bf16.f32 "
        "{%0,%1,%2,%3}, {%4,%5,%6,%7}, {%8,%9}, {%0,%1,%2,%3};"
        : "+f"(d[0]), "+f"(d[1]), "+f"(d[2]), "+f"(d[3])
        : "r"(a[0]), "r"(a[1]), "r"(a[2]), "r"(a[3]), "r"(b[0]), "r"(b[1]));
}
static __device__ __forceinline__ u32 pbf2(float lo, float hi) {
    __nv_bfloat162 t = __floats2bfloat162_rn(lo, hi);
    return *(u32*)&t;
}

// ---------- cluster helpers (baseline sm_90 PTX) ----------
static __device__ __forceinline__ u32 ctarank() {
    u32 r; asm("mov.u32 %0, %%cluster_ctarank;" : "=r"(r)); return r;
}
#define CLUSTER_SYNC() do { \
    asm volatile("barrier.cluster.arrive.aligned;" ::: "memory"); \
    asm volatile("barrier.cluster.wait.aligned;" ::: "memory"); } while (0)
#define MBAR_INIT(m, cnt) \
    asm volatile("mbarrier.init.shared.b64 [%0], %1;" :: "r"(m), "r"(cnt) : "memory")
static __device__ __forceinline__ u32 mapa_sh(u32 la, u32 rank) {
    u32 ra;
    asm volatile("mapa.shared::cluster.u32 %0, %1, %2;" : "=r"(ra) : "r"(la), "r"(rank));
    return ra;
}
static __device__ __forceinline__ void mbar_wait_cl(u32 m, u32 ph) {
    u32 done;
    do {
        asm volatile(
            "{\n\t.reg .pred p;\n\t"
            "mbarrier.try_wait.parity.acquire.cluster.shared::cta.b64 p, [%1], %2, 0x989680;\n\t"
            "selp.b32 %0, 1, 0, p;\n\t}"
            : "=r"(done) : "r"(m), "r"(ph) : "memory");
    } while (!done);
}

// ============================================================
// W pre-convert: f32 -> bf16 hi + bf16 lo (residual)
// ============================================================
__global__ void conv_w(const float* __restrict__ src,
                       __nv_bfloat16* __restrict__ hi,
                       __nv_bfloat16* __restrict__ lo, int n)
{
    int i = blockIdx.x * 256 + threadIdx.x;
    if (i < n) {
        float v = src[i];
        __nv_bfloat16 h = __float2bfloat16_rn(v);
        hi[i] = h;
        lo[i] = __float2bfloat16_rn(v - __bfloat162float(h));
    }
}

// ============================================================
// GEMM via mma.sync bf16x3 (unchanged from the 3310us round)
// ============================================================
#define GT_SMEM 65536

__global__ __launch_bounds__(256, 2) void gemm_mma(
    const float* __restrict__ X,
    const __nv_bfloat16* __restrict__ Whi,
    const __nv_bfloat16* __restrict__ Wlo,
    const float* __restrict__ bias,
    float* __restrict__ out, int K)
{
    extern __shared__ char sm[];
    const int tid = threadIdx.x, lane = tid & 31, wid = tid >> 5;
    const int mB = blockIdx.x * 128, nB = blockIdx.y * 128;
    const u32 smb = smem_u32(sm);
    const u32 AHI = 0, ALO = 16384, BHI = 32768, BLO = 49152;

    const int wm = wid & 3, wn = wid >> 2;
    const int m0w = wm * 32, n0w = wn * 64;

    float acc[2][8][4];
#pragma unroll
    for (int mt = 0; mt < 2; mt++)
#pragma unroll
        for (int nt = 0; nt < 8; nt++)
#pragma unroll
            for (int i = 0; i < 4; i++) acc[mt][nt][i] = 0.f;

#pragma unroll 1
    for (int kc = 0; kc < K; kc += 64) {
        if (kc) __syncthreads();
#pragma unroll
        for (int i = 0; i < 4; i++) {
            int g = tid + 256 * i;
            int row = g >> 3, grp = g & 7;
            const float* xp = X + (size_t)(mB + row) * K + kc + grp * 8;
            float4 v0 = *(const float4*)xp;
            float4 v1 = *(const float4*)(xp + 4);
            __nv_bfloat16 h0 = __float2bfloat16_rn(v0.x), h1 = __float2bfloat16_rn(v0.y);
            __nv_bfloat16 h2 = __float2bfloat16_rn(v0.z), h3 = __float2bfloat16_rn(v0.w);
            __nv_bfloat16 h4 = __float2bfloat16_rn(v1.x), h5 = __float2bfloat16_rn(v1.y);
            __nv_bfloat16 h6 = __float2bfloat16_rn(v1.z), h7 = __float2bfloat16_rn(v1.w);
            uint4 hq, lq;
            hq.x = (u32)__bfloat16_as_ushort(h0) | ((u32)__bfloat16_as_ushort(h1) << 16);
            hq.y = (u32)__bfloat16_as_ushort(h2) | ((u32)__bfloat16_as_ushort(h3) << 16);
            hq.z = (u32)__bfloat16_as_ushort(h4) | ((u32)__bfloat16_as_ushort(h5) << 16);
            hq.w = (u32)__bfloat16_as_ushort(h6) | ((u32)__bfloat16_as_ushort(h7) << 16);
            lq.x = pbf2(v0.x - __bfloat162float(h0), v0.y - __bfloat162float(h1));
            lq.y = pbf2(v0.z - __bfloat162float(h2), v0.w - __bfloat162float(h3));
            lq.z = pbf2(v1.x - __bfloat162float(h4), v1.y - __bfloat162float(h5));
            lq.w = pbf2(v1.z - __bfloat162float(h6), v1.w - __bfloat162float(h7));
            u32 off = (u32)(row * 128 + ((grp ^ (row & 7)) << 4));
            *(uint4*)(sm + AHI + off) = hq;
            *(uint4*)(sm + ALO + off) = lq;
        }
#pragma unroll
        for (int i = 0; i < 4; i++) {
            int g = tid + 256 * i;
            int row = g >> 3, grp = g & 7;
            size_t gix = (size_t)(nB + row) * K + kc + grp * 8;
            uint4 hv = *(const uint4*)(Whi + gix);
            uint4 lv = *(const uint4*)(Wlo + gix);
            u32 off = (u32)(row * 128 + ((grp ^ (row & 7)) << 4));
            *(uint4*)(sm + BHI + off) = hv;
            *(uint4*)(sm + BLO + off) = lv;
        }
        __syncthreads();

#pragma unroll
        for (int kt = 0; kt < 4; kt++) {
            u32 ah[2][4], al[2][4], bb[4][4];
#pragma unroll
            for (int mt = 0; mt < 2; mt++) {
                int sub = lane >> 3;
                int mrow = m0w + mt * 16 + (sub & 1) * 8 + (lane & 7);
                int c = kt * 2 + (sub >> 1);
                u32 ad = smb + mrow * 128 + ((u32)(c ^ (mrow & 7)) << 4);
                ldm_x4(ah[mt], ad + AHI);
                ldm_x4(al[mt], ad + ALO);
            }
            int subb = lane >> 3;
            u32 bad[4];
#pragma unroll
            for (int np = 0; np < 4; np++) {
                int nrow = n0w + np * 16 + (subb >> 1) * 8 + (lane & 7);
                int c = kt * 2 + (subb & 1);
                bad[np] = smb + nrow * 128 + ((u32)(c ^ (nrow & 7)) << 4);
                ldm_x4(bb[np], bad[np] + BHI);
            }
#pragma unroll
            for (int mt = 0; mt < 2; mt++)
#pragma unroll
                for (int nt = 0; nt < 8; nt++)
                    mma16816(acc[mt][nt], ah[mt], &bb[nt >> 1][(nt & 1) * 2]);
#pragma unroll
            for (int mt = 0; mt < 2; mt++)
#pragma unroll
                for (int nt = 0; nt < 8; nt++)
                    mma16816(acc[mt][nt], al[mt], &bb[nt >> 1][(nt & 1) * 2]);
#pragma unroll
            for (int np = 0; np < 4; np++)
                ldm_x4(bb[np], bad[np] + BLO);
#pragma unroll
            for (int mt = 0; mt < 2; mt++)
#pragma unroll
                for (int nt = 0; nt < 8; nt++)
                    mma16816(acc[mt][nt], ah[mt], &bb[nt >> 1][(nt & 1) * 2]);
        }
    }

#pragma unroll
    for (int mt = 0; mt < 2; mt++)
#pragma unroll
        for (int nt = 0; nt < 8; nt++) {
            int m = mB + m0w + mt * 16 + (lane >> 2);
            int n = nB + n0w + nt * 8 + (lane & 3) * 2;
            float2 bv = *(const float2*)&bias[n];
            float2 o0, o1;
            o0.x = acc[mt][nt][0] + bv.x;
            o0.y = acc[mt][nt][1] + bv.y;
            o1.x = acc[mt][nt][2] + bv.x;
            o1.y = acc[mt][nt][3] + bv.y;
            *(float2*)&out[(size_t)m * Gc + n] = o0;
            *(float2*)&out[(size_t)(m + 8) * Gc + n] = o1;
        }
}

// ============================================================
// LSTM recurrence: 2-CTA clusters, w_hh fully register-resident,
// split-wait + AGGREGATED ARRIVES: per step each pointwise warp
// (8 warps) issues ONE remote arrive (lane 0, after __syncwarp +
// fence.acq_rel.cluster) instead of 256 per-thread arrives.
// mbar count = 8.
// ============================================================
__global__ __launch_bounds__(512, 1) __cluster_dims__(2, 1, 1)
void lstm_rec(
    const float* __restrict__ xg, const float* __restrict__ whh,
    const float* __restrict__ h0, float* __restrict__ hout,
    const float* __restrict__ fcw, const float* __restrict__ fcb,
    float* __restrict__ outp, int is_l0)
{
    __shared__ float hs[2][4][128];        // [buf][batch][h]
    __shared__ float gb[4][4][256];        // [batch][kq][local row]
    __shared__ __align__(8) u64 mbar[2];

    const int tid = threadIdx.x;
    const u32 rank = ctarank();
    const u32 peer = rank ^ 1;
    const int cb0 = (blockIdx.x >> 1) * 4;     // first batch of cluster
    const int kq = tid >> 7, u = tid & 127;
    const int gg_ = u >> 6, po_ = u & 63;
    const int R0 = gg_ * 128 + (int)rank * 64 + po_;  // gate row (i/f)
    const int R1 = R0 + 256;                          // gate row (g/o)
    const int k0 = kq * 32;
    const bool peerk = ((u32)(kq >> 1) != rank);      // my k-half made by peer?

    // ---- w_hh fully into registers: 2 rows x 32 k = 64 regs ----
    u64 wr0[16], wr1[16];
#pragma unroll
    for (int q = 0; q < 8; q++) {
        ulonglong2 t0 = *(const ulonglong2*)&whh[(size_t)R0 * Hc + k0 + q * 4];
        wr0[2 * q] = t0.x; wr0[2 * q + 1] = t0.y;
        ulonglong2 t1 = *(const ulonglong2*)&whh[(size_t)R1 * Hc + k0 + q * 4];
        wr1[2 * q] = t1.x; wr1[2 * q + 1] = t1.y;
    }

    // ---- init h state (all 4 batches, full 128) + mbarriers ----
    hs[0][tid >> 7][tid & 127] = h0[(size_t)(cb0 + (tid >> 7)) * Hc + (tid & 127)];
    if (tid == 0) {
        MBAR_INIT(smem_u32(&mbar[0]), 8);   // one arrive per pointwise warp
        MBAR_INIT(smem_u32(&mbar[1]), 8);
    }
    __syncthreads();
    CLUSTER_SYNC();   // peers' mbar init + hs[0] ready

    // pointwise mapping (threads < 256): batch pb, local h offset pp
    const int pb = (tid >> 6) & 3, pp = tid & 63;
    float c = 0.f, hval = 0.f;

    // xg prefetch (kq==0 threads add xg for rows R0,R1, all 4 batches)
    float xc0[4], xc1[4], xn0[4], xn1[4];
#pragma unroll
    for (int b = 0; b < 4; b++) { xc0[b] = xc1[b] = xn0[b] = xn1[b] = 0.f; }
    if (kq == 0) {
#pragma unroll
        for (int b = 0; b < 4; b++) {
            xc0[b] = __ldg(&xg[(size_t)(cb0 + b) * Tc * Gc + R0]);
            xc1[b] = __ldg(&xg[(size_t)(cb0 + b) * Tc * Gc + R1]);
        }
    }

#pragma unroll 1
    for (int t = 0; t < Tc; t++) {
        // issue next-step xg LDGs before any waiting
        if (kq == 0) {
            int tn = (t + 1 < Tc) ? t + 1 : t;
#pragma unroll
            for (int b = 0; b < 4; b++) {
                xn0[b] = __ldg(&xg[((size_t)(cb0 + b) * Tc + tn) * Gc + R0]);
                xn1[b] = __ldg(&xg[((size_t)(cb0 + b) * Tc + tn) * Gc + R1]);
            }
        }

        // only peer-k warps wait for the peer's h-half of this step
        if (t > 0 && peerk)
            mbar_wait_cl(smem_u32(&mbar[t & 1]), (u32)(((t - 1) >> 1) & 1));

        // ---- matvec: 4 batches x 2 rows x 32 k, all-reg w ----
#pragma unroll
        for (int b = 0; b < 4; b++) {
            const float* hp = &hs[t & 1][b][k0];
            u64 A0 = 0, A1 = 0;
#pragma unroll
            for (int q = 0; q < 8; q++) {
                ulonglong2 ha = *(const ulonglong2*)(hp + q * 4);
                A0 = ffma2(wr0[2 * q], ha.x, A0);
                A0 = ffma2(wr0[2 * q + 1], ha.y, A0);
                A1 = ffma2(wr1[2 * q], ha.x, A1);
                A1 = ffma2(wr1[2 * q + 1], ha.y, A1);
            }
            float p0 = red2(A0), p1 = red2(A1);
            if (kq == 0) { p0 += xc0[b]; p1 += xc1[b]; }
            gb[b][kq][u] = p0;
            gb[b][kq][u + 128] = p1;
        }
        __syncthreads();

        // ---- pointwise: threads < 256, local h indices [64*rank, +64) ----
        if (tid < 256) {
            float gi = gb[pb][0][pp]       + gb[pb][1][pp]       + gb[pb][2][pp]       + gb[pb][3][pp];
            float gf = gb[pb][0][64 + pp]  + gb[pb][1][64 + pp]  + gb[pb][2][64 + pp]  + gb[pb][3][64 + pp];
            float g2 = gb[pb][0][128 + pp] + gb[pb][1][128 + pp] + gb[pb][2][128 + pp] + gb[pb][3][128 + pp];
            float go = gb[pb][0][192 + pp] + gb[pb][1][192 + pp] + gb[pb][2][192 + pp] + gb[pb][3][192 + pp];
            float fI = sigf(gi), fF = sigf(gf), fG = tanh_f(g2), fO = sigf(go);
            c = fF * c + fI * fG;
            hval = fO * tanh_f(c);

            int nb = (t + 1) & 1;
            int hix = (int)rank * 64 + pp;
            hs[nb][pb][hix] = hval;                       // local copy
            u32 la = smem_u32(&hs[nb][pb][hix]);
            u32 ra = mapa_sh(la, peer);                   // peer copy (DSMEM)
            asm volatile("st.shared::cluster.b32 [%0], %1;"
                         :: "r"(ra), "r"(__float_as_uint(hval)) : "memory");

            // ONE remote arrive per warp: syncwarp establishes HB from all
            // lanes' DSMEM stores to lane 0; the cluster-scope fence makes
            // them visible before the arrive the peer acquires on.
            __syncwarp(0xffffffffu);
            if ((tid & 31) == 0) {
                u32 rb = mapa_sh(smem_u32(&mbar[nb]), peer);
                asm volatile("fence.acq_rel.cluster;" ::: "memory");
                asm volatile("mbarrier.arrive.release.cluster.shared::cluster.b64 _, [%0];"
                             :: "r"(rb) : "memory");
            }
            if (is_l0)
                hout[((size_t)(cb0 + pb) * Tc + t) * Hc + hix] = hval;
        }
        __syncthreads();   // local h visible; gb reusable

#pragma unroll
        for (int b = 0; b < 4; b++) { xc0[b] = xn0[b]; xc1[b] = xn1[b]; }
    }

    // ---- fc head (layer 1): rank 0 needs peer's final h-half ----
    if (!is_l0 && rank == 0) {
        if (tid < 4) {
            mbar_wait_cl(smem_u32(&mbar[0]), 1u);  // final completion of mbar[0]
            float s = fcb[0];
            for (int i = 0; i < 128; i++) s += hs[0][tid][i] * fcw[i];
            outp[cb0 + tid] = s;
        }
    }
    CLUSTER_SYNC();   // keep smem alive for in-flight peer stores
}

extern "C" void kernel_launch(void* const* d_in, const int* in_sizes, int n_in,
                              void* d_out, int out_size) {
    const float* x    = (const float*)d_in[0];
    const float* h0   = (const float*)d_in[1];
    const float* wih0 = (const float*)d_in[2];
    const float* whh0 = (const float*)d_in[3];
    const float* b0_  = (const float*)d_in[4];
    const float* wih1 = (const float*)d_in[5];
    const float* whh1 = (const float*)d_in[6];
    const float* b1_  = (const float*)d_in[7];
    const float* fcw  = (const float*)d_in[8];
    const float* fcb  = (const float*)d_in[9];
    float* out = (float*)d_out;

    cudaFuncSetAttribute(gemm_mma, cudaFuncAttributeMaxDynamicSharedMemorySize, GT_SMEM);

    float *xgp, *h0sp;
    cudaGetSymbolAddress((void**)&xgp, g_xg);
    cudaGetSymbolAddress((void**)&h0sp, g_h0s);
    __nv_bfloat16 *whi0, *wlo0, *whi1, *wlo1;
    cudaGetSymbolAddress((void**)&whi0, g_whi0);
    cudaGetSymbolAddress((void**)&wlo0, g_wlo0);
    cudaGetSymbolAddress((void**)&whi1, g_whi1);
    cudaGetSymbolAddress((void**)&wlo1, g_wlo1);

    // pre-convert input-GEMM weights to bf16 hi/lo
    conv_w<<<(Gc * 64 + 255) / 256, 256>>>(wih0, whi0, wlo0, Gc * 64);
    conv_w<<<(Gc * Hc + 255) / 256, 256>>>(wih1, whi1, wlo1, Gc * Hc);

    dim3 ggrid(Mc / 128, Gc / 128);
    // layer 0 (K=64)
    gemm_mma<<<ggrid, 256, GT_SMEM>>>(x, whi0, wlo0, b0_, xgp, 64);
    lstm_rec<<<Bc / 2, 512>>>(xgp, whh0, h0, h0sp,
                              nullptr, nullptr, nullptr, 1);
    // layer 1 (K=128)
    gemm_mma<<<ggrid, 256, GT_SMEM>>>(h0sp, whi1, wlo1, b1_, xgp, 128);
    lstm_rec<<<Bc / 2, 512>>>(xgp, whh1, h0 + (size_t)Bc * Hc, nullptr,
                              fcw, fcb, out, 0);
}

// round 17
// speedup vs baseline: 1.3176x; 1.3176x over previous
#include <cuda_runtime.h>
#include <cuda_bf16.h>

typedef unsigned long long u64;
typedef unsigned int u32;

#define Bc 256
#define Tc 1024
#define Hc 128
#define Gc 512
#define Mc (Bc*Tc)

// Scratch (device globals: sanctioned workaround for the no-alloc rule)
__device__ float g_xg[(size_t)Mc * Gc];    // [B*T, 512] gate preactivations
__device__ float g_h0s[(size_t)Mc * Hc];   // [B*T, 128] layer-0 hidden states
__device__ __nv_bfloat16 g_whi0[Gc * 64];  // w_ih_0 bf16 hi
__device__ __nv_bfloat16 g_wlo0[Gc * 64];  // w_ih_0 bf16 lo
__device__ __nv_bfloat16 g_whi1[Gc * Hc];  // w_ih_1 bf16 hi
__device__ __nv_bfloat16 g_wlo1[Gc * Hc];  // w_ih_1 bf16 lo

// ---------- packed f32x2 helpers ----------
static __device__ __forceinline__ u64 ffma2(u64 a, u64 b, u64 c) {
    u64 d; asm("fma.rn.f32x2 %0, %1, %2, %3;" : "=l"(d) : "l"(a), "l"(b), "l"(c)); return d;
}
static __device__ __forceinline__ float red2(u64 v) {
    u32 a, b; asm("mov.b64 {%0, %1}, %2;" : "=r"(a), "=r"(b) : "l"(v));
    return __uint_as_float(a) + __uint_as_float(b);
}
static __device__ __forceinline__ float sigf(float x) {
    return __fdividef(1.f, 1.f + __expf(-x));
}
static __device__ __forceinline__ float tanh_f(float x) {
    return 1.f - __fdividef(2.f, 1.f + __expf(2.f * x));
}

// ---------- mma.sync helpers (baseline PTX, sm_80+) ----------
static __device__ __forceinline__ u32 smem_u32(const void* p) {
    u32 a;
    asm("{ .reg .u64 t; cvta.to.shared.u64 t, %1; cvt.u32.u64 %0, t; }"
        : "=r"(a) : "l"(p));
    return a;
}
static __device__ __forceinline__ void ldm_x4(u32* r, u32 a) {
    asm volatile("ldmatrix.sync.aligned.m8n8.x4.shared.b16 {%0,%1,%2,%3}, [%4];"
        : "=r"(r[0]), "=r"(r[1]), "=r"(r[2]), "=r"(r[3]) : "r"(a));
}
static __device__ __forceinline__ void mma16816(float* d, const u32* a, const u32* b) {
    asm volatile(
        "mma.sync.aligned.m16n8k16.row.col.f32.bf16.bf16.f32 "
        "{%0,%1,%2,%3}, {%4,%5,%6,%7}, {%8,%9}, {%0,%1,%2,%3};"
        : "+f"(d[0]), "+f"(d[1]), "+f"(d[2]), "+f"(d[3])
        : "r"(a[0]), "r"(a[1]), "r"(a[2]), "r"(a[3]), "r"(b[0]), "r"(b[1]));
}
static __device__ __forceinline__ u32 pbf2(float lo, float hi) {
    __nv_bfloat162 t = __floats2bfloat162_rn(lo, hi);
    return *(u32*)&t;
}
static __device__ __forceinline__ void cp_async16(u32 dst, const void* src) {
    asm volatile("cp.async.ca.shared.global [%0], [%1], 16;"
                 :: "r"(dst), "l"(src) : "memory");
}

// ============================================================
// W pre-convert: f32 -> bf16 hi + bf16 lo (residual)
// ============================================================
__global__ void conv_w(const float* __restrict__ src,
                       __nv_bfloat16* __restrict__ hi,
                       __nv_bfloat16* __restrict__ lo, int n)
{
    int i = blockIdx.x * 256 + threadIdx.x;
    if (i < n) {
        float v = src[i];
        __nv_bfloat16 h = __float2bfloat16_rn(v);
        hi[i] = h;
        lo[i] = __float2bfloat16_rn(v - __bfloat162float(h));
    }
}

// ============================================================
// GEMM via mma.sync bf16x3 (R11 structure; W tiles via cp.async)
// BM=128, BN=128 (grid.y=4), K chunked by 64. 256 thr, 8 warps.
// Products: AhiBhi + AloBhi + AhiBlo accumulated in f32.
// ============================================================
#define GT_SMEM 65536

__global__ __launch_bounds__(256, 2) void gemm_mma(
    const float* __restrict__ X,
    const __nv_bfloat16* __restrict__ Whi,
    const __nv_bfloat16* __restrict__ Wlo,
    const float* __restrict__ bias,
    float* __restrict__ out, int K)
{
    extern __shared__ char sm[];
    const int tid = threadIdx.x, lane = tid & 31, wid = tid >> 5;
    const int mB = blockIdx.x * 128, nB = blockIdx.y * 128;
    const u32 smb = smem_u32(sm);
    const u32 AHI = 0, ALO = 16384, BHI = 32768, BLO = 49152;

    const int wm = wid & 3, wn = wid >> 2;
    const int m0w = wm * 32, n0w = wn * 64;

    float acc[2][8][4];
#pragma unroll
    for (int mt = 0; mt < 2; mt++)
#pragma unroll
        for (int nt = 0; nt < 8; nt++)
#pragma unroll
            for (int i = 0; i < 4; i++) acc[mt][nt][i] = 0.f;

#pragma unroll 1
    for (int kc = 0; kc < K; kc += 64) {
        if (kc) __syncthreads();
        // ---- W tiles: cp.async direct gmem->smem (issued first, fly
        //      during the X conversion below) ----
#pragma unroll
        for (int i = 0; i < 4; i++) {
            int g = tid + 256 * i;
            int row = g >> 3, grp = g & 7;
            size_t gix = (size_t)(nB + row) * K + kc + grp * 8;
            u32 off = (u32)(row * 128 + ((grp ^ (row & 7)) << 4));
            cp_async16(smb + BHI + off, Whi + gix);
            cp_async16(smb + BLO + off, Wlo + gix);
        }
        // ---- X: load f32, split hi/lo, store swizzled bf16 ----
#pragma unroll
        for (int i = 0; i < 4; i++) {
            int g = tid + 256 * i;
            int row = g >> 3, grp = g & 7;
            const float* xp = X + (size_t)(mB + row) * K + kc + grp * 8;
            float4 v0 = *(const float4*)xp;
            float4 v1 = *(const float4*)(xp + 4);
            __nv_bfloat16 h0 = __float2bfloat16_rn(v0.x), h1 = __float2bfloat16_rn(v0.y);
            __nv_bfloat16 h2 = __float2bfloat16_rn(v0.z), h3 = __float2bfloat16_rn(v0.w);
            __nv_bfloat16 h4 = __float2bfloat16_rn(v1.x), h5 = __float2bfloat16_rn(v1.y);
            __nv_bfloat16 h6 = __float2bfloat16_rn(v1.z), h7 = __float2bfloat16_rn(v1.w);
            uint4 hq, lq;
            hq.x = (u32)__bfloat16_as_ushort(h0) | ((u32)__bfloat16_as_ushort(h1) << 16);
            hq.y = (u32)__bfloat16_as_ushort(h2) | ((u32)__bfloat16_as_ushort(h3) << 16);
            hq.z = (u32)__bfloat16_as_ushort(h4) | ((u32)__bfloat16_as_ushort(h5) << 16);
            hq.w = (u32)__bfloat16_as_ushort(h6) | ((u32)__bfloat16_as_ushort(h7) << 16);
            lq.x = pbf2(v0.x - __bfloat162float(h0), v0.y - __bfloat162float(h1));
            lq.y = pbf2(v0.z - __bfloat162float(h2), v0.w - __bfloat162float(h3));
            lq.z = pbf2(v1.x - __bfloat162float(h4), v1.y - __bfloat162float(h5));
            lq.w = pbf2(v1.z - __bfloat162float(h6), v1.w - __bfloat162float(h7));
            u32 off = (u32)(row * 128 + ((grp ^ (row & 7)) << 4));
            *(uint4*)(sm + AHI + off) = hq;
            *(uint4*)(sm + ALO + off) = lq;
        }
        asm volatile("cp.async.commit_group;" ::: "memory");
        asm volatile("cp.async.wait_group 0;" ::: "memory");
        __syncthreads();

#pragma unroll
        for (int kt = 0; kt < 4; kt++) {
            u32 ah[2][4], al[2][4], bb[4][4];
#pragma unroll
            for (int mt = 0; mt < 2; mt++) {
                int sub = lane >> 3;
                int mrow = m0w + mt * 16 + (sub & 1) * 8 + (lane & 7);
                int c = kt * 2 + (sub >> 1);
                u32 ad = smb + mrow * 128 + ((u32)(c ^ (mrow & 7)) << 4);
                ldm_x4(ah[mt], ad + AHI);
                ldm_x4(al[mt], ad + ALO);
            }
            int subb = lane >> 3;
            u32 bad[4];
#pragma unroll
            for (int np = 0; np < 4; np++) {
                int nrow = n0w + np * 16 + (subb >> 1) * 8 + (lane & 7);
                int c = kt * 2 + (subb & 1);
                bad[np] = smb + nrow * 128 + ((u32)(c ^ (nrow & 7)) << 4);
                ldm_x4(bb[np], bad[np] + BHI);
            }
#pragma unroll
            for (int mt = 0; mt < 2; mt++)
#pragma unroll
                for (int nt = 0; nt < 8; nt++)
                    mma16816(acc[mt][nt], ah[mt], &bb[nt >> 1][(nt & 1) * 2]);
#pragma unroll
            for (int mt = 0; mt < 2; mt++)
#pragma unroll
                for (int nt = 0; nt < 8; nt++)
                    mma16816(acc[mt][nt], al[mt], &bb[nt >> 1][(nt & 1) * 2]);
#pragma unroll
            for (int np = 0; np < 4; np++)
                ldm_x4(bb[np], bad[np] + BLO);
#pragma unroll
            for (int mt = 0; mt < 2; mt++)
#pragma unroll
                for (int nt = 0; nt < 8; nt++)
                    mma16816(acc[mt][nt], ah[mt], &bb[nt >> 1][(nt & 1) * 2]);
        }
    }

#pragma unroll
    for (int mt = 0; mt < 2; mt++)
#pragma unroll
        for (int nt = 0; nt < 8; nt++) {
            int m = mB + m0w + mt * 16 + (lane >> 2);
            int n = nB + n0w + nt * 8 + (lane & 3) * 2;
            float2 bv = *(const float2*)&bias[n];
            float2 o0, o1;
            o0.x = acc[mt][nt][0] + bv.x;
            o0.y = acc[mt][nt][1] + bv.y;
            o1.x = acc[mt][nt][2] + bv.x;
            o1.y = acc[mt][nt][3] + bv.y;
            *(float2*)&out[(size_t)m * Gc + n] = o0;
            *(float2*)&out[(size_t)(m + 8) * Gc + n] = o1;
        }
}

// ============================================================
// LSTM recurrence (exact R12, measured 1382us/launch):
// split-K over 512 threads, 1 CTA per 2 batches (128 CTAs).
// Thread (g = tid>>8, j = tid&255) owns rows {j, 256+j},
// k in [64g, 64g+64): half registers, half smem.
// ============================================================
#define REC_SMEM (2*8*512*16 + 2*2*128*4 + 2*2*512*4 + 256*4)  // 131072+2048+8192+1024

__global__ __launch_bounds__(512, 1) void lstm_rec(
    const float* __restrict__ xg, const float* __restrict__ whh,
    const float* __restrict__ h0, float* __restrict__ hout,
    const float* __restrict__ fcw, const float* __restrict__ fcb,
    float* __restrict__ outp, int is_l0)
{
    extern __shared__ char smraw[];
    ulonglong2* wsm = (ulonglong2*)smraw;            // [2 g][8 kq][512 rows]
    float* hs  = (float*)(smraw + 2 * 8 * 512 * 16); // [2 buf][2 batch][128]
    float* gb  = hs + 512;                           // [2 g][2 batch][512 rows]
    float* red = gb + 2048;                          // [256]

    const int tid = threadIdx.x;
    const int g = tid >> 8, j = tid & 255;
    const int b0 = blockIdx.x * 2;
    const int pb = (tid >> 7) & 1, p = tid & 127;    // pointwise mapping (tid<256)
    const int kb = g * 64;                            // group k-base

    // --- register weights: rows j, 256+j, k in [kb, kb+32) ---
    u64 wr0[16], wr1[16];
#pragma unroll
    for (int q = 0; q < 8; q++) {
        ulonglong2 t0 = *(const ulonglong2*)&whh[(size_t)j * Hc + kb + q * 4];
        wr0[2 * q] = t0.x; wr0[2 * q + 1] = t0.y;
        ulonglong2 t1 = *(const ulonglong2*)&whh[(size_t)(256 + j) * Hc + kb + q * 4];
        wr1[2 * q] = t1.x; wr1[2 * q + 1] = t1.y;
    }
    // --- smem weights: k in [kb+32, kb+64) ---
#pragma unroll
    for (int q = 0; q < 8; q++) {
        wsm[(g * 8 + q) * 512 + j] =
            *(const ulonglong2*)&whh[(size_t)j * Hc + kb + 32 + q * 4];
        wsm[(g * 8 + q) * 512 + 256 + j] =
            *(const ulonglong2*)&whh[(size_t)(256 + j) * Hc + kb + 32 + q * 4];
    }

    // --- init h (buffer 0), c = 0 ---
    if (tid < 256)
        hs[pb * 128 + p] = h0[(size_t)(b0 + pb) * Hc + p];
    float c = 0.f, hval = 0.f;

    const float* xA = xg + (size_t)b0 * Tc * Gc;
    const float* xB = xA + (size_t)Tc * Gc;
    float xa0 = 0.f, xa1 = 0.f, xb0 = 0.f, xb1 = 0.f;
    if (g == 0) {
        xa0 = __ldg(xA + j); xa1 = __ldg(xA + 256 + j);
        xb0 = __ldg(xB + j); xb1 = __ldg(xB + 256 + j);
    }
    __syncthreads();

#pragma unroll 1
    for (int t = 0; t < Tc; t++) {
        float na0, na1, nb0, nb1;
        if (g == 0) {
            size_t off = (size_t)((t + 1 < Tc) ? t + 1 : t) * Gc;
            na0 = __ldg(xA + off + j);       na1 = __ldg(xA + off + 256 + j);
            nb0 = __ldg(xB + off + j);       nb1 = __ldg(xB + off + 256 + j);
        }

        const float* hA = hs + (t & 1) * 256;
        const float* hB = hA + 128;
        u64 aA0 = 0, aB0 = 0, aA1 = 0, aB1 = 0;   // [row j / 256+j][batch A/B]
        // register half: k = kb + 4q
#pragma unroll
        for (int q = 0; q < 8; q++) {
            ulonglong2 ha = *(const ulonglong2*)(hA + kb + q * 4);
            ulonglong2 hb = *(const ulonglong2*)(hB + kb + q * 4);
            aA0 = ffma2(wr0[2*q], ha.x, aA0); aA0 = ffma2(wr0[2*q+1], ha.y, aA0);
            aB0 = ffma2(wr0[2*q], hb.x, aB0); aB0 = ffma2(wr0[2*q+1], hb.y, aB0);
            aA1 = ffma2(wr1[2*q], ha.x, aA1); aA1 = ffma2(wr1[2*q+1], ha.y, aA1);
            aB1 = ffma2(wr1[2*q], hb.x, aB1); aB1 = ffma2(wr1[2*q+1], hb.y, aB1);
        }
        // smem half: k = kb + 32 + 4q
#pragma unroll
        for (int q = 0; q < 8; q++) {
            ulonglong2 w0 = wsm[(g * 8 + q) * 512 + j];
            ulonglong2 w1 = wsm[(g * 8 + q) * 512 + 256 + j];
            ulonglong2 ha = *(const ulonglong2*)(hA + kb + 32 + q * 4);
            ulonglong2 hb = *(const ulonglong2*)(hB + kb + 32 + q * 4);
            aA0 = ffma2(w0.x, ha.x, aA0); aA0 = ffma2(w0.y, ha.y, aA0);
            aB0 = ffma2(w0.x, hb.x, aB0); aB0 = ffma2(w0.y, hb.y, aB0);
            aA1 = ffma2(w1.x, ha.x, aA1); aA1 = ffma2(w1.y, ha.y, aA1);
            aB1 = ffma2(w1.x, hb.x, aB1); aB1 = ffma2(w1.y, hb.y, aB1);
        }
        float pA0 = red2(aA0), pA1 = red2(aA1);
        float pB0 = red2(aB0), pB1 = red2(aB1);
        if (g == 0) { pA0 += xa0; pA1 += xa1; pB0 += xb0; pB1 += xb1; }
        gb[g * 1024 + j]             = pA0;
        gb[g * 1024 + 256 + j]       = pA1;
        gb[g * 1024 + 512 + j]       = pB0;
        gb[g * 1024 + 512 + 256 + j] = pB1;
        __syncthreads();

        // pointwise: threads < 256, (pb, p); sum the two k-half partials
        if (tid < 256) {
            float gi = gb[pb * 512 + p]       + gb[1024 + pb * 512 + p];
            float gf = gb[pb * 512 + 128 + p] + gb[1024 + pb * 512 + 128 + p];
            float gg = gb[pb * 512 + 256 + p] + gb[1024 + pb * 512 + 256 + p];
            float go = gb[pb * 512 + 384 + p] + gb[1024 + pb * 512 + 384 + p];
            float fI = sigf(gi), fF = sigf(gf), fG = tanh_f(gg), fO = sigf(go);
            c = fF * c + fI * fG;
            hval = fO * tanh_f(c);
            hs[((t + 1) & 1) * 256 + pb * 128 + p] = hval;
            if (is_l0)
                hout[((size_t)(b0 + pb) * Tc + t) * Hc + p] = hval;
        }
        if (g == 0) { xa0 = na0; xa1 = na1; xb0 = nb0; xb1 = nb1; }
        __syncthreads();
    }

    if (!is_l0) {
        if (tid < 256)
            red[pb * 128 + p] = hval * fcw[p];
        __syncthreads();
        if (tid < 2) {
            float s = fcb[0];
            for (int i = 0; i < 128; i++) s += red[tid * 128 + i];
            outp[b0 + tid] = s;
        }
    }
}

extern "C" void kernel_launch(void* const* d_in, const int* in_sizes, int n_in,
                              void* d_out, int out_size) {
    const float* x    = (const float*)d_in[0];
    const float* h0   = (const float*)d_in[1];
    const float* wih0 = (const float*)d_in[2];
    const float* whh0 = (const float*)d_in[3];
    const float* b0_  = (const float*)d_in[4];
    const float* wih1 = (const float*)d_in[5];
    const float* whh1 = (const float*)d_in[6];
    const float* b1_  = (const float*)d_in[7];
    const float* fcw  = (const float*)d_in[8];
    const float* fcb  = (const float*)d_in[9];
    float* out = (float*)d_out;

    cudaFuncSetAttribute(gemm_mma, cudaFuncAttributeMaxDynamicSharedMemorySize, GT_SMEM);
    cudaFuncSetAttribute(lstm_rec, cudaFuncAttributeMaxDynamicSharedMemorySize, REC_SMEM);

    float *xgp, *h0sp;
    cudaGetSymbolAddress((void**)&xgp, g_xg);
    cudaGetSymbolAddress((void**)&h0sp, g_h0s);
    __nv_bfloat16 *whi0, *wlo0, *whi1, *wlo1;
    cudaGetSymbolAddress((void**)&whi0, g_whi0);
    cudaGetSymbolAddress((void**)&wlo0, g_wlo0);
    cudaGetSymbolAddress((void**)&whi1, g_whi1);
    cudaGetSymbolAddress((void**)&wlo1, g_wlo1);

    // pre-convert input-GEMM weights to bf16 hi/lo
    conv_w<<<(Gc * 64 + 255) / 256, 256>>>(wih0, whi0, wlo0, Gc * 64);
    conv_w<<<(Gc * Hc + 255) / 256, 256>>>(wih1, whi1, wlo1, Gc * Hc);

    dim3 ggrid(Mc / 128, Gc / 128);
    // layer 0 (K=64)
    gemm_mma<<<ggrid, 256, GT_SMEM>>>(x, whi0, wlo0, b0_, xgp, 64);
    lstm_rec<<<Bc / 2, 512, REC_SMEM>>>(xgp, whh0, h0, h0sp,
                                        nullptr, nullptr, nullptr, 1);
    // layer 1 (K=128)
    gemm_mma<<<ggrid, 256, GT_SMEM>>>(h0sp, whi1, wlo1, b1_, xgp, 128);
    lstm_rec<<<Bc / 2, 512, REC_SMEM>>>(xgp, whh1, h0 + (size_t)Bc * Hc, nullptr,
                                        fcw, fcb, out, 0);
}